// round 15
// baseline (speedup 1.0000x reference)
#include <cuda_runtime.h>
#include <cuda_fp16.h>
#include <cstdint>

#define DI __device__ __forceinline__

// ---------------------------------------------------------------------------
// Problem constants
// ---------------------------------------------------------------------------
constexpr int M_DIM = 16384;
constexpr int N_DIM = 4096;
constexpr int K_DIM = 4096;

constexpr int BM = 128, BN = 128, BK = 64;      // CTA tile
constexpr int NT = K_DIM / BK;                  // 64 k-tiles
constexpr int NSTAGE = 3;
constexpr int A_BYTES = BM * BK * 2;            // 16384
constexpr int B_BYTES = BN * BK * 2;            // 16384
constexpr int STAGE_BYTES = A_BYTES + B_BYTES;  // 32768
constexpr int SMEM_MBAR  = NSTAGE * STAGE_BYTES;       // 98304
constexpr int SMEM_TOTAL = SMEM_MBAR + 64;             // + 6 mbarriers

constexpr int X_BLOCKS = (M_DIM * K_DIM) / 4 / 256;    // 65536
constexpr int W_BLOCKS = (N_DIM * K_DIM) / 16384;      // 1024

// ---------------------------------------------------------------------------
// Scratch (device globals: allocation-free per harness rules)
// ---------------------------------------------------------------------------
__device__ __half g_A[(size_t)M_DIM * K_DIM];   // 134 MB  (x in fp16)
__device__ __half g_B[(size_t)N_DIM * K_DIM];   // 33.5 MB (nf4-dequant W in fp16)

// ---------------------------------------------------------------------------
// NF4 tables (fp32, identical arithmetic to reference)
// ---------------------------------------------------------------------------
__constant__ float NF4_CODE[16] = {
    -1.0f, -0.6961928009986877f, -0.5250730514526367f, -0.39491748809814453f,
    -0.28444138169288635f, -0.18477343022823334f, -0.09105003625154495f, 0.0f,
    0.07958029955625534f, 0.16093020141124725f, 0.24611230194568634f,
    0.33791524171829224f, 0.44070982933044434f, 0.5626170039176941f,
    0.7229568362236023f, 1.0f};

__constant__ float NF4_BOUND[15] = {
    (-1.0f + -0.6961928009986877f) * 0.5f,
    (-0.6961928009986877f + -0.5250730514526367f) * 0.5f,
    (-0.5250730514526367f + -0.39491748809814453f) * 0.5f,
    (-0.39491748809814453f + -0.28444138169288635f) * 0.5f,
    (-0.28444138169288635f + -0.18477343022823334f) * 0.5f,
    (-0.18477343022823334f + -0.09105003625154495f) * 0.5f,
    (-0.09105003625154495f + 0.0f) * 0.5f,
    (0.0f + 0.07958029955625534f) * 0.5f,
    (0.07958029955625534f + 0.16093020141124725f) * 0.5f,
    (0.16093020141124725f + 0.24611230194568634f) * 0.5f,
    (0.24611230194568634f + 0.33791524171829224f) * 0.5f,
    (0.33791524171829224f + 0.44070982933044434f) * 0.5f,
    (0.44070982933044434f + 0.5626170039176941f) * 0.5f,
    (0.5626170039176941f + 0.7229568362236023f) * 0.5f,
    (0.7229568362236023f + 1.0f) * 0.5f};

// ---------------------------------------------------------------------------
// PTX helpers (all baseline sm_80/90-class: legal on plain sm_103 target)
// ---------------------------------------------------------------------------
DI uint32_t smem_u32(const void* p) {
    uint32_t a;
    asm("{ .reg .u64 t; cvta.to.shared.u64 t, %1; cvt.u32.u64 %0, t; }" : "=r"(a) : "l"(p));
    return a;
}
DI void cp_async16(uint32_t dst, const void* src) {
    asm volatile("cp.async.cg.shared.global [%0], [%1], 16;\n" :: "r"(dst), "l"(src));
}
// All prior cp.asyncs of this thread arrive (once) on the mbarrier when done.
DI void cp_async_arrive(uint32_t mbar) {
    asm volatile("cp.async.mbarrier.arrive.noinc.shared.b64 [%0];" :: "r"(mbar) : "memory");
}
DI void mbar_init(uint32_t a, uint32_t cnt) {
    asm volatile("mbarrier.init.shared.b64 [%0], %1;" :: "r"(a), "r"(cnt) : "memory");
}
DI void mbar_arrive(uint32_t a) {
    asm volatile("mbarrier.arrive.shared.b64 _, [%0];" :: "r"(a) : "memory");
}
DI void mbar_wait(uint32_t a, uint32_t parity) {
    uint32_t done;
    asm volatile(
        "{\n\t.reg .pred p;\n\t"
        "mbarrier.try_wait.parity.acquire.cta.shared::cta.b64 p, [%1], %2;\n\t"
        "selp.b32 %0, 1, 0, p;\n\t}"
        : "=r"(done) : "r"(a), "r"(parity) : "memory");
    if (!done) {
        asm volatile(
            "{\n\t.reg .pred P1;\n"
            "W_%=:\n\t"
            "mbarrier.try_wait.parity.acquire.cta.shared::cta.b64 P1, [%0], %1, 0x989680;\n\t"
            "@P1 bra.uni D_%=;\n\t"
            "bra.uni W_%=;\n"
            "D_%=:\n\t}"
            :: "r"(a), "r"(parity) : "memory");
    }
}

DI void ldmatrix_x4(uint32_t r[4], uint32_t addr) {
    asm volatile("ldmatrix.sync.aligned.m8n8.x4.shared.b16 {%0,%1,%2,%3}, [%4];"
                 : "=r"(r[0]), "=r"(r[1]), "=r"(r[2]), "=r"(r[3]) : "r"(addr));
}
DI void mma_16816(float c[4], const uint32_t a[4], uint32_t b0, uint32_t b1) {
    asm volatile(
        "mma.sync.aligned.m16n8k16.row.col.f32.f16.f16.f32 "
        "{%0,%1,%2,%3}, {%4,%5,%6,%7}, {%8,%9}, {%0,%1,%2,%3};"
        : "+f"(c[0]), "+f"(c[1]), "+f"(c[2]), "+f"(c[3])
        : "r"(a[0]), "r"(a[1]), "r"(a[2]), "r"(a[3]), "r"(b0), "r"(b1));
}

// ---------------------------------------------------------------------------
// Fused prep kernel: blocks [0, X_BLOCKS) convert x fp32->fp16 (DRAM-bound);
// blocks [X_BLOCKS, X_BLOCKS+W_BLOCKS) do NF4 quant->dequant of W (ALU-heavy,
// hides under the x path's bandwidth phase). One launch instead of two.
// ---------------------------------------------------------------------------
__global__ void prep_fused_kernel(const float* __restrict__ x,
                                  const float* __restrict__ w) {
    if (blockIdx.x < X_BLOCKS) {
        // ---- x conversion path (identical math to prep_x_kernel) ----
        size_t i4 = (size_t)blockIdx.x * blockDim.x + threadIdx.x;
        const float4 v = reinterpret_cast<const float4*>(x)[i4];
        __half2 h0 = make_half2(__float2half_rn(v.x), __float2half_rn(v.y));
        __half2 h1 = make_half2(__float2half_rn(v.z), __float2half_rn(v.w));
        uint2 p = make_uint2(*reinterpret_cast<uint32_t*>(&h0),
                             *reinterpret_cast<uint32_t*>(&h1));
        reinterpret_cast<uint2*>(g_A)[i4] = p;
        return;
    }

    // ---- W dequant path (identical math to prep_w_kernel) ----
    __shared__ float red[256];
    const int t = threadIdx.x;
    const int wblk = blockIdx.x - X_BLOCKS;
    const size_t base = (size_t)wblk * 16384 + (size_t)t * 64;

    // per-64-block absmax
    float amax = 0.f;
#pragma unroll 4
    for (int i = 0; i < 16; i++) {
        float4 v = reinterpret_cast<const float4*>(w + base)[i];
        amax = fmaxf(amax, fmaxf(fmaxf(fabsf(v.x), fabsf(v.y)),
                                 fmaxf(fabsf(v.z), fabsf(v.w))));
    }
    red[t] = amax;
    __syncthreads();
    for (int s = 128; s > 0; s >>= 1) {
        if (t < s) red[t] = fmaxf(red[t], red[t + s]);
        __syncthreads();
    }
    float s_amax = red[0];
    if (s_amax == 0.f) s_amax = 1.f;

    // double-quantized scale (round-half-even like jnp.round; IEEE ops)
    float q8    = rintf(__fmul_rn(__fdiv_rn(amax, s_amax), 127.0f));
    float scale = __fmul_rn(__fdiv_rn(q8, 127.0f), s_amax);
    float sa    = (amax == 0.f) ? 1.f : amax;

    __half* orow = g_B + base;   // g_B layout == w layout [n][k]
#pragma unroll 2
    for (int i = 0; i < 16; i++) {
        float4 v = reinterpret_cast<const float4*>(w + base)[i];
        float f[4] = {v.x, v.y, v.z, v.w};
        __half h[4];
#pragma unroll
        for (int j = 0; j < 4; j++) {
            float norm = __fdiv_rn(f[j], sa);
            int idx = 0;
#pragma unroll
            for (int b = 0; b < 15; b++) idx += (norm > NF4_BOUND[b]) ? 1 : 0;
            float wdq = __fmul_rn(NF4_CODE[idx], scale);   // exact ref value
            h[j] = __float2half_rn(wdq);
        }
        uint2 p;
        p.x = (uint32_t)__half_as_ushort(h[0]) | ((uint32_t)__half_as_ushort(h[1]) << 16);
        p.y = (uint32_t)__half_as_ushort(h[2]) | ((uint32_t)__half_as_ushort(h[3]) << 16);
        *reinterpret_cast<uint2*>(orow + i * 4) = p;
    }
}

// ---------------------------------------------------------------------------
// Kernel 3: mma.sync fp16 GEMM (fp32 accum), 128x128x64 CTA tile, 3-stage
// mbarrier producer/consumer pipeline without per-k-tile __syncthreads
// (exact R10 schedule — the measured local optimum: batched LDGSTS burst
// before the full-wait, per-thread count-128 arrives on both barriers).
// 2 CTAs/SM, 4 warps, 64x64 warp tiles.
// ---------------------------------------------------------------------------
DI void load_stage(int kt, int tid, int m0, int n0, uint32_t sbase) {
    const int s = kt % NSTAGE;
    const uint32_t sA = sbase + s * STAGE_BYTES;
    const uint32_t sB = sA + A_BYTES;
    const int k0 = kt * BK;
#pragma unroll
    for (int i = 0; i < 8; i++) {                 // A: 1024 16B chunks
        int c = tid + i * 128;
        int r = c >> 3, col = c & 7;
        uint32_t so = (uint32_t)(r * 128 + col * 16) ^ ((uint32_t)(r & 7) << 4);
        cp_async16(sA + so, &g_A[(size_t)(m0 + r) * K_DIM + (k0 + col * 8)]);
    }
#pragma unroll
    for (int i = 0; i < 8; i++) {                 // B: 1024 16B chunks
        int c = tid + i * 128;
        int r = c >> 3, col = c & 7;
        uint32_t so = (uint32_t)(r * 128 + col * 16) ^ ((uint32_t)(r & 7) << 4);
        cp_async16(sB + so, &g_B[(size_t)(n0 + r) * K_DIM + (k0 + col * 8)]);
    }
}

__global__ void __launch_bounds__(128, 2) gemm_kernel(float* __restrict__ out) {
    extern __shared__ __align__(128) char smem_raw[];
    const uint32_t sbase = smem_u32(smem_raw);
    const int tid  = threadIdx.x;
    const int lane = tid & 31;
    const int wid  = tid >> 5;
    const int wm   = wid >> 1;        // 0..1  (64-row slab)
    const int wn   = wid & 1;         // 0..1  (64-col slab)

    // mbarrier layout: full[s] at +s*16, empty[s] at +s*16+8 (both count 128)
    const uint32_t mb = sbase + SMEM_MBAR;

    // grouped raster: supertile of 8 m-tiles x 32 n-tiles (~1 wave);
    // working set A 8MB + B 33MB stays in L2.
    const int pid = blockIdx.x;
    const int tm = (pid >> 8) * 8 + (pid & 7);    // 0..127
    const int tn = (pid & 255) >> 3;              // 0..31
    const int m0 = tm * BM;
    const int n0 = tn * BN;

    float acc[4][8][4];
#pragma unroll
    for (int i = 0; i < 4; i++)
#pragma unroll
        for (int j = 0; j < 8; j++)
#pragma unroll
            for (int q = 0; q < 4; q++) acc[i][j][q] = 0.f;

    if (tid == 0) {
#pragma unroll
        for (int s = 0; s < NSTAGE; s++) {
            mbar_init(mb + s * 16, 128);       // full[s]
            mbar_init(mb + s * 16 + 8, 128);   // empty[s]
        }
    }
    __syncthreads();   // barriers visible before any cp.async targets them

    // prologue: fill stages 0,1 (fresh empty barriers -> no wait needed)
#pragma unroll
    for (int p = 0; p < NSTAGE - 1; p++) {
        load_stage(p, tid, m0, n0, sbase);
        cp_async_arrive(mb + p * 16);          // full[p]
    }

    // ldmatrix per-lane address components (constant over k-loop)
    const int a_row  = wm * 64 + (lane & 15);                       // + mt*16
    const uint32_t a_kh = (uint32_t)(lane >> 4) * 16;
    const int b_row  = wn * 64 + ((lane >> 4) << 3) + (lane & 7);   // + p*16
    const uint32_t b_kh = (uint32_t)((lane >> 3) & 1) * 16;

    // producer cursor: next fill is stage 2, phase 1 (first wait passes on
    // fresh barrier). consumer cursor: stage 0, phase 0.
    int pc_s = NSTAGE - 1, pc_ph = 1;
    int cc_s = 0, cc_ph = 0;

#pragma unroll 1
    for (int kt = 0; kt < NT; kt++) {
        if (kt + NSTAGE - 1 < NT) {
            mbar_wait(mb + pc_s * 16 + 8, (uint32_t)pc_ph);   // empty[pc_s]
            load_stage(kt + NSTAGE - 1, tid, m0, n0, sbase);
            cp_async_arrive(mb + pc_s * 16);                  // full[pc_s]
            if (++pc_s == NSTAGE) { pc_s = 0; pc_ph ^= 1; }
        }

        mbar_wait(mb + cc_s * 16, (uint32_t)cc_ph);           // full[cc_s]
        const uint32_t sA = sbase + cc_s * STAGE_BYTES;
        const uint32_t sB = sA + A_BYTES;

#pragma unroll
        for (int ks = 0; ks < 4; ks++) {
            const uint32_t kca = (uint32_t)(ks * 32) + a_kh;
            const uint32_t kcb = (uint32_t)(ks * 32) + b_kh;
            uint32_t a[4][4];
#pragma unroll
            for (int mt = 0; mt < 4; mt++) {
                int r = a_row + mt * 16;
                uint32_t so = (uint32_t)(r * 128) + (kca ^ ((uint32_t)(r & 7) << 4));
                ldmatrix_x4(a[mt], sA + so);
            }
            uint32_t b[4][4];
#pragma unroll
            for (int p = 0; p < 4; p++) {
                int r = b_row + p * 16;
                uint32_t so = (uint32_t)(r * 128) + (kcb ^ ((uint32_t)(r & 7) << 4));
                ldmatrix_x4(b[p], sB + so);
            }
#pragma unroll
            for (int mt = 0; mt < 4; mt++)
#pragma unroll
                for (int p = 0; p < 4; p++) {
                    mma_16816(acc[mt][2 * p],     a[mt], b[p][0], b[p][1]);
                    mma_16816(acc[mt][2 * p + 1], a[mt], b[p][2], b[p][3]);
                }
        }

        mbar_arrive(mb + cc_s * 16 + 8);                      // empty[cc_s]
        if (++cc_s == NSTAGE) { cc_s = 0; cc_ph ^= 1; }
    }

    // epilogue: direct fp32 stores (float2 per fragment half)
    const int gm = m0 + wm * 64 + (lane >> 2);
    const int gn = n0 + wn * 64 + (lane & 3) * 2;
#pragma unroll
    for (int mt = 0; mt < 4; mt++) {
#pragma unroll
        for (int nt = 0; nt < 8; nt++) {
            float* p0 = out + (size_t)(gm + mt * 16) * N_DIM + gn + nt * 8;
            float* p1 = out + (size_t)(gm + mt * 16 + 8) * N_DIM + gn + nt * 8;
            *reinterpret_cast<float2*>(p0) = make_float2(acc[mt][nt][0], acc[mt][nt][1]);
            *reinterpret_cast<float2*>(p1) = make_float2(acc[mt][nt][2], acc[mt][nt][3]);
        }
    }
}

// ---------------------------------------------------------------------------
// Launch
// ---------------------------------------------------------------------------
extern "C" void kernel_launch(void* const* d_in, const int* in_sizes, int n_in,
                              void* d_out, int out_size) {
    const float* x = (const float*)d_in[0];
    const float* w = (const float*)d_in[1];
    if (n_in >= 2 && in_sizes[0] < in_sizes[1]) {   // defensive: x is larger
        x = (const float*)d_in[1];
        w = (const float*)d_in[0];
    }
    float* out = (float*)d_out;

    static bool attr_set = false;
    if (!attr_set) {
        cudaFuncSetAttribute(gemm_kernel,
                             cudaFuncAttributeMaxDynamicSharedMemorySize, SMEM_TOTAL);
        attr_set = true;
    }

    prep_fused_kernel<<<X_BLOCKS + W_BLOCKS, 256>>>(x, w);
    gemm_kernel<<<(M_DIM / BM) * (N_DIM / BN), 128, SMEM_TOTAL>>>(out);
}

// round 16
// speedup vs baseline: 1.5529x; 1.5529x over previous
#include <cuda_runtime.h>
#include <cuda_fp16.h>
#include <cstdint>

#define DI __device__ __forceinline__

// ---------------------------------------------------------------------------
// Problem constants
// ---------------------------------------------------------------------------
constexpr int M_DIM = 16384;
constexpr int N_DIM = 4096;
constexpr int K_DIM = 4096;

constexpr int BM = 128, BN = 128, BK = 64;      // CTA tile
constexpr int NT = K_DIM / BK;                  // 64 k-tiles
constexpr int NSTAGE = 3;
constexpr int A_BYTES = BM * BK * 2;            // 16384
constexpr int B_BYTES = BN * BK * 2;            // 16384
constexpr int STAGE_BYTES = A_BYTES + B_BYTES;  // 32768
constexpr int SMEM_MBAR  = NSTAGE * STAGE_BYTES;       // 98304
constexpr int SMEM_TOTAL = SMEM_MBAR + 64;             // + 6 mbarriers

// ---------------------------------------------------------------------------
// Scratch (device globals: allocation-free per harness rules)
// ---------------------------------------------------------------------------
__device__ __half g_A[(size_t)M_DIM * K_DIM];   // 134 MB  (x in fp16)
__device__ __half g_B[(size_t)N_DIM * K_DIM];   // 33.5 MB (nf4-dequant W in fp16)

// ---------------------------------------------------------------------------
// NF4 tables (fp32, identical arithmetic to reference)
// ---------------------------------------------------------------------------
__constant__ float NF4_CODE[16] = {
    -1.0f, -0.6961928009986877f, -0.5250730514526367f, -0.39491748809814453f,
    -0.28444138169288635f, -0.18477343022823334f, -0.09105003625154495f, 0.0f,
    0.07958029955625534f, 0.16093020141124725f, 0.24611230194568634f,
    0.33791524171829224f, 0.44070982933044434f, 0.5626170039176941f,
    0.7229568362236023f, 1.0f};

__constant__ float NF4_BOUND[15] = {
    (-1.0f + -0.6961928009986877f) * 0.5f,
    (-0.6961928009986877f + -0.5250730514526367f) * 0.5f,
    (-0.5250730514526367f + -0.39491748809814453f) * 0.5f,
    (-0.39491748809814453f + -0.28444138169288635f) * 0.5f,
    (-0.28444138169288635f + -0.18477343022823334f) * 0.5f,
    (-0.18477343022823334f + -0.09105003625154495f) * 0.5f,
    (-0.09105003625154495f + 0.0f) * 0.5f,
    (0.0f + 0.07958029955625534f) * 0.5f,
    (0.07958029955625534f + 0.16093020141124725f) * 0.5f,
    (0.16093020141124725f + 0.24611230194568634f) * 0.5f,
    (0.24611230194568634f + 0.33791524171829224f) * 0.5f,
    (0.33791524171829224f + 0.44070982933044434f) * 0.5f,
    (0.44070982933044434f + 0.5626170039176941f) * 0.5f,
    (0.5626170039176941f + 0.7229568362236023f) * 0.5f,
    (0.7229568362236023f + 1.0f) * 0.5f};

// ---------------------------------------------------------------------------
// PTX helpers (all baseline sm_80/90-class: legal on plain sm_103 target)
// ---------------------------------------------------------------------------
DI uint32_t smem_u32(const void* p) {
    uint32_t a;
    asm("{ .reg .u64 t; cvta.to.shared.u64 t, %1; cvt.u32.u64 %0, t; }" : "=r"(a) : "l"(p));
    return a;
}
DI void cp_async16(uint32_t dst, const void* src) {
    asm volatile("cp.async.cg.shared.global [%0], [%1], 16;\n" :: "r"(dst), "l"(src));
}
// All prior cp.asyncs of this thread arrive (once) on the mbarrier when done.
DI void cp_async_arrive(uint32_t mbar) {
    asm volatile("cp.async.mbarrier.arrive.noinc.shared.b64 [%0];" :: "r"(mbar) : "memory");
}
DI void mbar_init(uint32_t a, uint32_t cnt) {
    asm volatile("mbarrier.init.shared.b64 [%0], %1;" :: "r"(a), "r"(cnt) : "memory");
}
DI void mbar_arrive(uint32_t a) {
    asm volatile("mbarrier.arrive.shared.b64 _, [%0];" :: "r"(a) : "memory");
}
DI void mbar_wait(uint32_t a, uint32_t parity) {
    uint32_t done;
    asm volatile(
        "{\n\t.reg .pred p;\n\t"
        "mbarrier.try_wait.parity.acquire.cta.shared::cta.b64 p, [%1], %2;\n\t"
        "selp.b32 %0, 1, 0, p;\n\t}"
        : "=r"(done) : "r"(a), "r"(parity) : "memory");
    if (!done) {
        asm volatile(
            "{\n\t.reg .pred P1;\n"
            "W_%=:\n\t"
            "mbarrier.try_wait.parity.acquire.cta.shared::cta.b64 P1, [%0], %1, 0x989680;\n\t"
            "@P1 bra.uni D_%=;\n\t"
            "bra.uni W_%=;\n"
            "D_%=:\n\t}"
            :: "r"(a), "r"(parity) : "memory");
    }
}

DI void ldmatrix_x4(uint32_t r[4], uint32_t addr) {
    asm volatile("ldmatrix.sync.aligned.m8n8.x4.shared.b16 {%0,%1,%2,%3}, [%4];"
                 : "=r"(r[0]), "=r"(r[1]), "=r"(r[2]), "=r"(r[3]) : "r"(addr));
}
DI void mma_16816(float c[4], const uint32_t a[4], uint32_t b0, uint32_t b1) {
    asm volatile(
        "mma.sync.aligned.m16n8k16.row.col.f32.f16.f16.f32 "
        "{%0,%1,%2,%3}, {%4,%5,%6,%7}, {%8,%9}, {%0,%1,%2,%3};"
        : "+f"(c[0]), "+f"(c[1]), "+f"(c[2]), "+f"(c[3])
        : "r"(a[0]), "r"(a[1]), "r"(a[2]), "r"(a[3]), "r"(b0), "r"(b1));
}

// ---------------------------------------------------------------------------
// Kernel 1: x (fp32) -> fp16 g_A.  4 independent float4 loads per thread
// (grid-stride by blockDim) so the LSU has MLP=4 per thread and conversions
// overlap the later loads.
// ---------------------------------------------------------------------------
__global__ void prep_x_kernel(const float* __restrict__ x) {
    const size_t base = (size_t)blockIdx.x * (blockDim.x * 4) + threadIdx.x;
    float4 v[4];
#pragma unroll
    for (int j = 0; j < 4; j++)
        v[j] = reinterpret_cast<const float4*>(x)[base + j * blockDim.x];
#pragma unroll
    for (int j = 0; j < 4; j++) {
        __half2 h0 = make_half2(__float2half_rn(v[j].x), __float2half_rn(v[j].y));
        __half2 h1 = make_half2(__float2half_rn(v[j].z), __float2half_rn(v[j].w));
        uint2 p = make_uint2(*reinterpret_cast<uint32_t*>(&h0),
                             *reinterpret_cast<uint32_t*>(&h1));
        reinterpret_cast<uint2*>(g_A)[base + j * blockDim.x] = p;
    }
}

// ---------------------------------------------------------------------------
// Kernel 2: NF4 quant->dequant of W (exact reference math) -> fp16 g_B[n][k]
// One CTA per scale block (256 quant blocks of 64 = 16384 elems = 4 rows).
// ---------------------------------------------------------------------------
__global__ void prep_w_kernel(const float* __restrict__ w) {
    __shared__ float red[256];
    const int t = threadIdx.x;
    const size_t base = (size_t)blockIdx.x * 16384 + (size_t)t * 64;

    // per-64-block absmax
    float amax = 0.f;
#pragma unroll 4
    for (int i = 0; i < 16; i++) {
        float4 v = reinterpret_cast<const float4*>(w + base)[i];
        amax = fmaxf(amax, fmaxf(fmaxf(fabsf(v.x), fabsf(v.y)),
                                 fmaxf(fabsf(v.z), fabsf(v.w))));
    }
    red[t] = amax;
    __syncthreads();
    for (int s = 128; s > 0; s >>= 1) {
        if (t < s) red[t] = fmaxf(red[t], red[t + s]);
        __syncthreads();
    }
    float s_amax = red[0];
    if (s_amax == 0.f) s_amax = 1.f;

    // double-quantized scale (round-half-even like jnp.round; IEEE ops)
    float q8    = rintf(__fmul_rn(__fdiv_rn(amax, s_amax), 127.0f));
    float scale = __fmul_rn(__fdiv_rn(q8, 127.0f), s_amax);
    float sa    = (amax == 0.f) ? 1.f : amax;

    __half* orow = g_B + base;   // g_B layout == w layout [n][k]
#pragma unroll 2
    for (int i = 0; i < 16; i++) {
        float4 v = reinterpret_cast<const float4*>(w + base)[i];
        float f[4] = {v.x, v.y, v.z, v.w};
        __half h[4];
#pragma unroll
        for (int j = 0; j < 4; j++) {
            float norm = __fdiv_rn(f[j], sa);
            int idx = 0;
#pragma unroll
            for (int b = 0; b < 15; b++) idx += (norm > NF4_BOUND[b]) ? 1 : 0;
            float wdq = __fmul_rn(NF4_CODE[idx], scale);   // exact ref value
            h[j] = __float2half_rn(wdq);
        }
        uint2 p;
        p.x = (uint32_t)__half_as_ushort(h[0]) | ((uint32_t)__half_as_ushort(h[1]) << 16);
        p.y = (uint32_t)__half_as_ushort(h[2]) | ((uint32_t)__half_as_ushort(h[3]) << 16);
        *reinterpret_cast<uint2*>(orow + i * 4) = p;
    }
}

// ---------------------------------------------------------------------------
// Kernel 3: mma.sync fp16 GEMM (fp32 accum), 128x128x64 CTA tile, 3-stage
// mbarrier producer/consumer pipeline without per-k-tile __syncthreads
// (exact R10 schedule — the measured local optimum). 2 CTAs/SM, 4 warps,
// 64x64 warp tiles.
// ---------------------------------------------------------------------------
DI void load_stage(int kt, int tid, int m0, int n0, uint32_t sbase) {
    const int s = kt % NSTAGE;
    const uint32_t sA = sbase + s * STAGE_BYTES;
    const uint32_t sB = sA + A_BYTES;
    const int k0 = kt * BK;
#pragma unroll
    for (int i = 0; i < 8; i++) {                 // A: 1024 16B chunks
        int c = tid + i * 128;
        int r = c >> 3, col = c & 7;
        uint32_t so = (uint32_t)(r * 128 + col * 16) ^ ((uint32_t)(r & 7) << 4);
        cp_async16(sA + so, &g_A[(size_t)(m0 + r) * K_DIM + (k0 + col * 8)]);
    }
#pragma unroll
    for (int i = 0; i < 8; i++) {                 // B: 1024 16B chunks
        int c = tid + i * 128;
        int r = c >> 3, col = c & 7;
        uint32_t so = (uint32_t)(r * 128 + col * 16) ^ ((uint32_t)(r & 7) << 4);
        cp_async16(sB + so, &g_B[(size_t)(n0 + r) * K_DIM + (k0 + col * 8)]);
    }
}

__global__ void __launch_bounds__(128, 2) gemm_kernel(float* __restrict__ out) {
    extern __shared__ __align__(128) char smem_raw[];
    const uint32_t sbase = smem_u32(smem_raw);
    const int tid  = threadIdx.x;
    const int lane = tid & 31;
    const int wid  = tid >> 5;
    const int wm   = wid >> 1;        // 0..1  (64-row slab)
    const int wn   = wid & 1;         // 0..1  (64-col slab)

    // mbarrier layout: full[s] at +s*16, empty[s] at +s*16+8 (both count 128)
    const uint32_t mb = sbase + SMEM_MBAR;

    // grouped raster: supertile of 8 m-tiles x 32 n-tiles (~1 wave);
    // working set A 8MB + B 33MB stays in L2.
    const int pid = blockIdx.x;
    const int tm = (pid >> 8) * 8 + (pid & 7);    // 0..127
    const int tn = (pid & 255) >> 3;              // 0..31
    const int m0 = tm * BM;
    const int n0 = tn * BN;

    float acc[4][8][4];
#pragma unroll
    for (int i = 0; i < 4; i++)
#pragma unroll
        for (int j = 0; j < 8; j++)
#pragma unroll
            for (int q = 0; q < 4; q++) acc[i][j][q] = 0.f;

    if (tid == 0) {
#pragma unroll
        for (int s = 0; s < NSTAGE; s++) {
            mbar_init(mb + s * 16, 128);       // full[s]
            mbar_init(mb + s * 16 + 8, 128);   // empty[s]
        }
    }
    __syncthreads();   // barriers visible before any cp.async targets them

    // prologue: fill stages 0,1 (fresh empty barriers -> no wait needed)
#pragma unroll
    for (int p = 0; p < NSTAGE - 1; p++) {
        load_stage(p, tid, m0, n0, sbase);
        cp_async_arrive(mb + p * 16);          // full[p]
    }

    // ldmatrix per-lane address components (constant over k-loop)
    const int a_row  = wm * 64 + (lane & 15);                       // + mt*16
    const uint32_t a_kh = (uint32_t)(lane >> 4) * 16;
    const int b_row  = wn * 64 + ((lane >> 4) << 3) + (lane & 7);   // + p*16
    const uint32_t b_kh = (uint32_t)((lane >> 3) & 1) * 16;

    // producer cursor: next fill is stage 2, phase 1 (first wait passes on
    // fresh barrier). consumer cursor: stage 0, phase 0.
    int pc_s = NSTAGE - 1, pc_ph = 1;
    int cc_s = 0, cc_ph = 0;

#pragma unroll 1
    for (int kt = 0; kt < NT; kt++) {
        if (kt + NSTAGE - 1 < NT) {
            mbar_wait(mb + pc_s * 16 + 8, (uint32_t)pc_ph);   // empty[pc_s]
            load_stage(kt + NSTAGE - 1, tid, m0, n0, sbase);
            cp_async_arrive(mb + pc_s * 16);                  // full[pc_s]
            if (++pc_s == NSTAGE) { pc_s = 0; pc_ph ^= 1; }
        }

        mbar_wait(mb + cc_s * 16, (uint32_t)cc_ph);           // full[cc_s]
        const uint32_t sA = sbase + cc_s * STAGE_BYTES;
        const uint32_t sB = sA + A_BYTES;

#pragma unroll
        for (int ks = 0; ks < 4; ks++) {
            const uint32_t kca = (uint32_t)(ks * 32) + a_kh;
            const uint32_t kcb = (uint32_t)(ks * 32) + b_kh;
            uint32_t a[4][4];
#pragma unroll
            for (int mt = 0; mt < 4; mt++) {
                int r = a_row + mt * 16;
                uint32_t so = (uint32_t)(r * 128) + (kca ^ ((uint32_t)(r & 7) << 4));
                ldmatrix_x4(a[mt], sA + so);
            }
            uint32_t b[4][4];
#pragma unroll
            for (int p = 0; p < 4; p++) {
                int r = b_row + p * 16;
                uint32_t so = (uint32_t)(r * 128) + (kcb ^ ((uint32_t)(r & 7) << 4));
                ldmatrix_x4(b[p], sB + so);
            }
#pragma unroll
            for (int mt = 0; mt < 4; mt++)
#pragma unroll
                for (int p = 0; p < 4; p++) {
                    mma_16816(acc[mt][2 * p],     a[mt], b[p][0], b[p][1]);
                    mma_16816(acc[mt][2 * p + 1], a[mt], b[p][2], b[p][3]);
                }
        }

        mbar_arrive(mb + cc_s * 16 + 8);                      // empty[cc_s]
        if (++cc_s == NSTAGE) { cc_s = 0; cc_ph ^= 1; }
    }

    // epilogue: direct fp32 stores (float2 per fragment half)
    const int gm = m0 + wm * 64 + (lane >> 2);
    const int gn = n0 + wn * 64 + (lane & 3) * 2;
#pragma unroll
    for (int mt = 0; mt < 4; mt++) {
#pragma unroll
        for (int nt = 0; nt < 8; nt++) {
            float* p0 = out + (size_t)(gm + mt * 16) * N_DIM + gn + nt * 8;
            float* p1 = out + (size_t)(gm + mt * 16 + 8) * N_DIM + gn + nt * 8;
            *reinterpret_cast<float2*>(p0) = make_float2(acc[mt][nt][0], acc[mt][nt][1]);
            *reinterpret_cast<float2*>(p1) = make_float2(acc[mt][nt][2], acc[mt][nt][3]);
        }
    }
}

// ---------------------------------------------------------------------------
// Launch
// ---------------------------------------------------------------------------
extern "C" void kernel_launch(void* const* d_in, const int* in_sizes, int n_in,
                              void* d_out, int out_size) {
    const float* x = (const float*)d_in[0];
    const float* w = (const float*)d_in[1];
    if (n_in >= 2 && in_sizes[0] < in_sizes[1]) {   // defensive: x is larger
        x = (const float*)d_in[1];
        w = (const float*)d_in[0];
    }
    float* out = (float*)d_out;

    static bool attr_set = false;
    if (!attr_set) {
        cudaFuncSetAttribute(gemm_kernel,
                             cudaFuncAttributeMaxDynamicSharedMemorySize, SMEM_TOTAL);
        attr_set = true;
    }

    prep_x_kernel<<<(M_DIM * K_DIM) / 4 / (256 * 4), 256>>>(x);   // 16384 blocks
    prep_w_kernel<<<(N_DIM * K_DIM) / 16384, 256>>>(w);
    gemm_kernel<<<(M_DIM / BM) * (N_DIM / BN), 128, SMEM_TOTAL>>>(out);
}

// round 17
// speedup vs baseline: 1.5531x; 1.0001x over previous
#include <cuda_runtime.h>
#include <cuda_fp16.h>
#include <cstdint>

#define DI __device__ __forceinline__

// ---------------------------------------------------------------------------
// Problem constants
// ---------------------------------------------------------------------------
constexpr int M_DIM = 16384;
constexpr int N_DIM = 4096;
constexpr int K_DIM = 4096;

constexpr int BM = 128, BN = 128, BK = 64;      // CTA tile
constexpr int NT = K_DIM / BK;                  // 64 k-tiles
constexpr int NSTAGE = 3;
constexpr int A_BYTES = BM * BK * 2;            // 16384
constexpr int B_BYTES = BN * BK * 2;            // 16384
constexpr int STAGE_BYTES = A_BYTES + B_BYTES;  // 32768
constexpr int SMEM_MBAR  = NSTAGE * STAGE_BYTES;       // 98304
constexpr int SMEM_TOTAL = SMEM_MBAR + 64;             // + 6 mbarriers

// ---------------------------------------------------------------------------
// Scratch (device globals: allocation-free per harness rules)
// ---------------------------------------------------------------------------
__device__ __half g_A[(size_t)M_DIM * K_DIM];   // 134 MB  (x in fp16)
__device__ __half g_B[(size_t)N_DIM * K_DIM];   // 33.5 MB (nf4-dequant W in fp16)

// ---------------------------------------------------------------------------
// NF4 tables (fp32, identical arithmetic to reference)
// ---------------------------------------------------------------------------
__constant__ float NF4_CODE[16] = {
    -1.0f, -0.6961928009986877f, -0.5250730514526367f, -0.39491748809814453f,
    -0.28444138169288635f, -0.18477343022823334f, -0.09105003625154495f, 0.0f,
    0.07958029955625534f, 0.16093020141124725f, 0.24611230194568634f,
    0.33791524171829224f, 0.44070982933044434f, 0.5626170039176941f,
    0.7229568362236023f, 1.0f};

__constant__ float NF4_BOUND[15] = {
    (-1.0f + -0.6961928009986877f) * 0.5f,
    (-0.6961928009986877f + -0.5250730514526367f) * 0.5f,
    (-0.5250730514526367f + -0.39491748809814453f) * 0.5f,
    (-0.39491748809814453f + -0.28444138169288635f) * 0.5f,
    (-0.28444138169288635f + -0.18477343022823334f) * 0.5f,
    (-0.18477343022823334f + -0.09105003625154495f) * 0.5f,
    (-0.09105003625154495f + 0.0f) * 0.5f,
    (0.0f + 0.07958029955625534f) * 0.5f,
    (0.07958029955625534f + 0.16093020141124725f) * 0.5f,
    (0.16093020141124725f + 0.24611230194568634f) * 0.5f,
    (0.24611230194568634f + 0.33791524171829224f) * 0.5f,
    (0.33791524171829224f + 0.44070982933044434f) * 0.5f,
    (0.44070982933044434f + 0.5626170039176941f) * 0.5f,
    (0.5626170039176941f + 0.7229568362236023f) * 0.5f,
    (0.7229568362236023f + 1.0f) * 0.5f};

// ---------------------------------------------------------------------------
// PTX helpers (all baseline sm_80/90-class: legal on plain sm_103 target)
// ---------------------------------------------------------------------------
DI uint32_t smem_u32(const void* p) {
    uint32_t a;
    asm("{ .reg .u64 t; cvta.to.shared.u64 t, %1; cvt.u32.u64 %0, t; }" : "=r"(a) : "l"(p));
    return a;
}
DI void cp_async16(uint32_t dst, const void* src) {
    asm volatile("cp.async.cg.shared.global [%0], [%1], 16;\n" :: "r"(dst), "l"(src));
}
// All prior cp.asyncs of this thread arrive (once) on the mbarrier when done.
DI void cp_async_arrive(uint32_t mbar) {
    asm volatile("cp.async.mbarrier.arrive.noinc.shared.b64 [%0];" :: "r"(mbar) : "memory");
}
DI void mbar_init(uint32_t a, uint32_t cnt) {
    asm volatile("mbarrier.init.shared.b64 [%0], %1;" :: "r"(a), "r"(cnt) : "memory");
}
DI void mbar_arrive(uint32_t a) {
    asm volatile("mbarrier.arrive.shared.b64 _, [%0];" :: "r"(a) : "memory");
}
DI void mbar_wait(uint32_t a, uint32_t parity) {
    uint32_t done;
    asm volatile(
        "{\n\t.reg .pred p;\n\t"
        "mbarrier.try_wait.parity.acquire.cta.shared::cta.b64 p, [%1], %2;\n\t"
        "selp.b32 %0, 1, 0, p;\n\t}"
        : "=r"(done) : "r"(a), "r"(parity) : "memory");
    if (!done) {
        asm volatile(
            "{\n\t.reg .pred P1;\n"
            "W_%=:\n\t"
            "mbarrier.try_wait.parity.acquire.cta.shared::cta.b64 P1, [%0], %1, 0x989680;\n\t"
            "@P1 bra.uni D_%=;\n\t"
            "bra.uni W_%=;\n"
            "D_%=:\n\t}"
            :: "r"(a), "r"(parity) : "memory");
    }
}

DI void ldmatrix_x4(uint32_t r[4], uint32_t addr) {
    asm volatile("ldmatrix.sync.aligned.m8n8.x4.shared.b16 {%0,%1,%2,%3}, [%4];"
                 : "=r"(r[0]), "=r"(r[1]), "=r"(r[2]), "=r"(r[3]) : "r"(addr));
}
DI void mma_16816(float c[4], const uint32_t a[4], uint32_t b0, uint32_t b1) {
    asm volatile(
        "mma.sync.aligned.m16n8k16.row.col.f32.f16.f16.f32 "
        "{%0,%1,%2,%3}, {%4,%5,%6,%7}, {%8,%9}, {%0,%1,%2,%3};"
        : "+f"(c[0]), "+f"(c[1]), "+f"(c[2]), "+f"(c[3])
        : "r"(a[0]), "r"(a[1]), "r"(a[2]), "r"(a[3]), "r"(b0), "r"(b1));
}

// ---------------------------------------------------------------------------
// Kernel 1: x (fp32) -> fp16 g_A.  8 independent float4 loads per thread
// (strided by blockDim) so the LSU has MLP=8 per thread and conversions
// overlap the later loads.
// ---------------------------------------------------------------------------
__global__ void prep_x_kernel(const float* __restrict__ x) {
    const size_t base = (size_t)blockIdx.x * (blockDim.x * 8) + threadIdx.x;
    float4 v[8];
#pragma unroll
    for (int j = 0; j < 8; j++)
        v[j] = reinterpret_cast<const float4*>(x)[base + j * blockDim.x];
#pragma unroll
    for (int j = 0; j < 8; j++) {
        __half2 h0 = make_half2(__float2half_rn(v[j].x), __float2half_rn(v[j].y));
        __half2 h1 = make_half2(__float2half_rn(v[j].z), __float2half_rn(v[j].w));
        uint2 p = make_uint2(*reinterpret_cast<uint32_t*>(&h0),
                             *reinterpret_cast<uint32_t*>(&h1));
        reinterpret_cast<uint2*>(g_A)[base + j * blockDim.x] = p;
    }
}

// ---------------------------------------------------------------------------
// Kernel 2: NF4 quant->dequant of W (exact reference math) -> fp16 g_B[n][k]
// One CTA per scale block (256 quant blocks of 64 = 16384 elems = 4 rows).
// ---------------------------------------------------------------------------
__global__ void prep_w_kernel(const float* __restrict__ w) {
    __shared__ float red[256];
    const int t = threadIdx.x;
    const size_t base = (size_t)blockIdx.x * 16384 + (size_t)t * 64;

    // per-64-block absmax
    float amax = 0.f;
#pragma unroll 4
    for (int i = 0; i < 16; i++) {
        float4 v = reinterpret_cast<const float4*>(w + base)[i];
        amax = fmaxf(amax, fmaxf(fmaxf(fabsf(v.x), fabsf(v.y)),
                                 fmaxf(fabsf(v.z), fabsf(v.w))));
    }
    red[t] = amax;
    __syncthreads();
    for (int s = 128; s > 0; s >>= 1) {
        if (t < s) red[t] = fmaxf(red[t], red[t + s]);
        __syncthreads();
    }
    float s_amax = red[0];
    if (s_amax == 0.f) s_amax = 1.f;

    // double-quantized scale (round-half-even like jnp.round; IEEE ops)
    float q8    = rintf(__fmul_rn(__fdiv_rn(amax, s_amax), 127.0f));
    float scale = __fmul_rn(__fdiv_rn(q8, 127.0f), s_amax);
    float sa    = (amax == 0.f) ? 1.f : amax;

    __half* orow = g_B + base;   // g_B layout == w layout [n][k]
#pragma unroll 2
    for (int i = 0; i < 16; i++) {
        float4 v = reinterpret_cast<const float4*>(w + base)[i];
        float f[4] = {v.x, v.y, v.z, v.w};
        __half h[4];
#pragma unroll
        for (int j = 0; j < 4; j++) {
            float norm = __fdiv_rn(f[j], sa);
            int idx = 0;
#pragma unroll
            for (int b = 0; b < 15; b++) idx += (norm > NF4_BOUND[b]) ? 1 : 0;
            float wdq = __fmul_rn(NF4_CODE[idx], scale);   // exact ref value
            h[j] = __float2half_rn(wdq);
        }
        uint2 p;
        p.x = (uint32_t)__half_as_ushort(h[0]) | ((uint32_t)__half_as_ushort(h[1]) << 16);
        p.y = (uint32_t)__half_as_ushort(h[2]) | ((uint32_t)__half_as_ushort(h[3]) << 16);
        *reinterpret_cast<uint2*>(orow + i * 4) = p;
    }
}

// ---------------------------------------------------------------------------
// Kernel 3: mma.sync fp16 GEMM (fp32 accum), 128x128x64 CTA tile, 3-stage
// mbarrier producer/consumer pipeline without per-k-tile __syncthreads
// (exact R10 schedule — the measured local optimum). 2 CTAs/SM, 4 warps,
// 64x64 warp tiles.
// ---------------------------------------------------------------------------
DI void load_stage(int kt, int tid, int m0, int n0, uint32_t sbase) {
    const int s = kt % NSTAGE;
    const uint32_t sA = sbase + s * STAGE_BYTES;
    const uint32_t sB = sA + A_BYTES;
    const int k0 = kt * BK;
#pragma unroll
    for (int i = 0; i < 8; i++) {                 // A: 1024 16B chunks
        int c = tid + i * 128;
        int r = c >> 3, col = c & 7;
        uint32_t so = (uint32_t)(r * 128 + col * 16) ^ ((uint32_t)(r & 7) << 4);
        cp_async16(sA + so, &g_A[(size_t)(m0 + r) * K_DIM + (k0 + col * 8)]);
    }
#pragma unroll
    for (int i = 0; i < 8; i++) {                 // B: 1024 16B chunks
        int c = tid + i * 128;
        int r = c >> 3, col = c & 7;
        uint32_t so = (uint32_t)(r * 128 + col * 16) ^ ((uint32_t)(r & 7) << 4);
        cp_async16(sB + so, &g_B[(size_t)(n0 + r) * K_DIM + (k0 + col * 8)]);
    }
}

__global__ void __launch_bounds__(128, 2) gemm_kernel(float* __restrict__ out) {
    extern __shared__ __align__(128) char smem_raw[];
    const uint32_t sbase = smem_u32(smem_raw);
    const int tid  = threadIdx.x;
    const int lane = tid & 31;
    const int wid  = tid >> 5;
    const int wm   = wid >> 1;        // 0..1  (64-row slab)
    const int wn   = wid & 1;         // 0..1  (64-col slab)

    // mbarrier layout: full[s] at +s*16, empty[s] at +s*16+8 (both count 128)
    const uint32_t mb = sbase + SMEM_MBAR;

    // grouped raster: supertile of 8 m-tiles x 32 n-tiles (~1 wave);
    // working set A 8MB + B 33MB stays in L2.
    const int pid = blockIdx.x;
    const int tm = (pid >> 8) * 8 + (pid & 7);    // 0..127
    const int tn = (pid & 255) >> 3;              // 0..31
    const int m0 = tm * BM;
    const int n0 = tn * BN;

    float acc[4][8][4];
#pragma unroll
    for (int i = 0; i < 4; i++)
#pragma unroll
        for (int j = 0; j < 8; j++)
#pragma unroll
            for (int q = 0; q < 4; q++) acc[i][j][q] = 0.f;

    if (tid == 0) {
#pragma unroll
        for (int s = 0; s < NSTAGE; s++) {
            mbar_init(mb + s * 16, 128);       // full[s]
            mbar_init(mb + s * 16 + 8, 128);   // empty[s]
        }
    }
    __syncthreads();   // barriers visible before any cp.async targets them

    // prologue: fill stages 0,1 (fresh empty barriers -> no wait needed)
#pragma unroll
    for (int p = 0; p < NSTAGE - 1; p++) {
        load_stage(p, tid, m0, n0, sbase);
        cp_async_arrive(mb + p * 16);          // full[p]
    }

    // ldmatrix per-lane address components (constant over k-loop)
    const int a_row  = wm * 64 + (lane & 15);                       // + mt*16
    const uint32_t a_kh = (uint32_t)(lane >> 4) * 16;
    const int b_row  = wn * 64 + ((lane >> 4) << 3) + (lane & 7);   // + p*16
    const uint32_t b_kh = (uint32_t)((lane >> 3) & 1) * 16;

    // producer cursor: next fill is stage 2, phase 1 (first wait passes on
    // fresh barrier). consumer cursor: stage 0, phase 0.
    int pc_s = NSTAGE - 1, pc_ph = 1;
    int cc_s = 0, cc_ph = 0;

#pragma unroll 1
    for (int kt = 0; kt < NT; kt++) {
        if (kt + NSTAGE - 1 < NT) {
            mbar_wait(mb + pc_s * 16 + 8, (uint32_t)pc_ph);   // empty[pc_s]
            load_stage(kt + NSTAGE - 1, tid, m0, n0, sbase);
            cp_async_arrive(mb + pc_s * 16);                  // full[pc_s]
            if (++pc_s == NSTAGE) { pc_s = 0; pc_ph ^= 1; }
        }

        mbar_wait(mb + cc_s * 16, (uint32_t)cc_ph);           // full[cc_s]
        const uint32_t sA = sbase + cc_s * STAGE_BYTES;
        const uint32_t sB = sA + A_BYTES;

#pragma unroll
        for (int ks = 0; ks < 4; ks++) {
            const uint32_t kca = (uint32_t)(ks * 32) + a_kh;
            const uint32_t kcb = (uint32_t)(ks * 32) + b_kh;
            uint32_t a[4][4];
#pragma unroll
            for (int mt = 0; mt < 4; mt++) {
                int r = a_row + mt * 16;
                uint32_t so = (uint32_t)(r * 128) + (kca ^ ((uint32_t)(r & 7) << 4));
                ldmatrix_x4(a[mt], sA + so);
            }
            uint32_t b[4][4];
#pragma unroll
            for (int p = 0; p < 4; p++) {
                int r = b_row + p * 16;
                uint32_t so = (uint32_t)(r * 128) + (kcb ^ ((uint32_t)(r & 7) << 4));
                ldmatrix_x4(b[p], sB + so);
            }
#pragma unroll
            for (int mt = 0; mt < 4; mt++)
#pragma unroll
                for (int p = 0; p < 4; p++) {
                    mma_16816(acc[mt][2 * p],     a[mt], b[p][0], b[p][1]);
                    mma_16816(acc[mt][2 * p + 1], a[mt], b[p][2], b[p][3]);
                }
        }

        mbar_arrive(mb + cc_s * 16 + 8);                      // empty[cc_s]
        if (++cc_s == NSTAGE) { cc_s = 0; cc_ph ^= 1; }
    }

    // epilogue: direct fp32 stores (float2 per fragment half)
    const int gm = m0 + wm * 64 + (lane >> 2);
    const int gn = n0 + wn * 64 + (lane & 3) * 2;
#pragma unroll
    for (int mt = 0; mt < 4; mt++) {
#pragma unroll
        for (int nt = 0; nt < 8; nt++) {
            float* p0 = out + (size_t)(gm + mt * 16) * N_DIM + gn + nt * 8;
            float* p1 = out + (size_t)(gm + mt * 16 + 8) * N_DIM + gn + nt * 8;
            *reinterpret_cast<float2*>(p0) = make_float2(acc[mt][nt][0], acc[mt][nt][1]);
            *reinterpret_cast<float2*>(p1) = make_float2(acc[mt][nt][2], acc[mt][nt][3]);
        }
    }
}

// ---------------------------------------------------------------------------
// Launch
// ---------------------------------------------------------------------------
extern "C" void kernel_launch(void* const* d_in, const int* in_sizes, int n_in,
                              void* d_out, int out_size) {
    const float* x = (const float*)d_in[0];
    const float* w = (const float*)d_in[1];
    if (n_in >= 2 && in_sizes[0] < in_sizes[1]) {   // defensive: x is larger
        x = (const float*)d_in[1];
        w = (const float*)d_in[0];
    }
    float* out = (float*)d_out;

    static bool attr_set = false;
    if (!attr_set) {
        cudaFuncSetAttribute(gemm_kernel,
                             cudaFuncAttributeMaxDynamicSharedMemorySize, SMEM_TOTAL);
        attr_set = true;
    }

    prep_x_kernel<<<(M_DIM * K_DIM) / 4 / (256 * 8), 256>>>(x);   // 8192 blocks
    prep_w_kernel<<<(N_DIM * K_DIM) / 16384, 256>>>(w);
    gemm_kernel<<<(M_DIM / BM) * (N_DIM / BN), 128, SMEM_TOTAL>>>(out);
}